// round 1
// baseline (speedup 1.0000x reference)
#include <cuda_runtime.h>

#define Bb 8
#define Nn 1024
#define Ee 10

__device__ float g_Ppart[Bb * 8 * Nn];
__device__ float g_Mpart[Bb * 8 * Nn];
__device__ float g_base[Bb * Nn * Ee];
__device__ float g_h[2][Bb * Ee * Nn];   // ping-pong, transposed [b][e][i]
__device__ float g_S[Bb * Ee];
__device__ float g_wp[Ee * Ee];

__global__ void stage_wp_kernel(const float* __restrict__ wp) {
    if (threadIdx.x < Ee * Ee) g_wp[threadIdx.x] = wp[threadIdx.x];
}

__global__ void __launch_bounds__(256) colsum_kernel(const float* __restrict__ w) {
    int i  = blockIdx.x * 256 + threadIdx.x;
    int jc = blockIdx.y;
    int b  = blockIdx.z;
    const float* p = w + (size_t)(b * Nn + jc * 128) * Nn + i;
    float sp = 0.f, sm = 0.f;
#pragma unroll 8
    for (int j = 0; j < 128; j++) {
        float v = p[(size_t)j * Nn];
        sp += fmaxf(v, 0.f);
        sm += fminf(v, 0.f);
    }
    g_Ppart[(b * 8 + jc) * Nn + i] = sp;
    g_Mpart[(b * 8 + jc) * Nn + i] = sm;
}

__global__ void __launch_bounds__(256) base_kernel(
    const float* __restrict__ feat,
    const float* __restrict__ ws,
    const float* __restrict__ wnb,
    const float* __restrict__ ew,
    const float* __restrict__ wp)
{
    int idx = blockIdx.x * 256 + threadIdx.x;
    int b = idx >> 10, i = idx & 1023;
    if (idx < Bb * Ee) g_S[idx] = 0.f;

    float P = 0.f, M = 0.f;
#pragma unroll
    for (int c = 0; c < 8; c++) {
        P += g_Ppart[(b * 8 + c) * Nn + i];
        M += g_Mpart[(b * 8 + c) * Nn + i];
    }
    float f = feat[idx];

    float ewv[Ee];
#pragma unroll
    for (int e = 0; e < Ee; e++) ewv[e] = ew[e];

    float emb1[Ee];
#pragma unroll
    for (int e = 0; e < Ee; e++) {
        float cP = 0.f, cM = 0.f;
#pragma unroll
        for (int g = 0; g < Ee; g++) {
            float wv = wnb[e * Ee + g];
            cP += wv * fmaxf(ewv[g], 0.f);
            cM += wv * fminf(ewv[g], 0.f);
        }
        float basev = f * ws[e] + cP * P + cM * M;
        g_base[idx * Ee + e] = basev;
        emb1[e] = fmaxf(basev, 0.f);
    }
#pragma unroll
    for (int e = 0; e < Ee; e++) {
        float hv = 0.f;
#pragma unroll
        for (int g = 0; g < Ee; g++) hv += wp[e * Ee + g] * emb1[g];
        g_h[0][(b * Ee + e) * Nn + i] = hv;
    }
}

__global__ void __launch_bounds__(256) iter_kernel(
    const float* __restrict__ A,
    int src,
    float* __restrict__ emb_out,
    int last)
{
    __shared__ float sh[Ee * Nn];
    __shared__ float wps[Ee * Ee];
    int b = blockIdx.y;
    int tid = threadIdx.x;

    const float* hin = g_h[src];
    float* hout = g_h[src ^ 1];

    const float4* hsrc = (const float4*)(hin + b * Ee * Nn);
    float4* hdst = (float4*)sh;
#pragma unroll
    for (int k = 0; k < 10; k++) hdst[tid + k * 256] = hsrc[tid + k * 256];
    if (tid < Ee * Ee) wps[tid] = g_wp[tid];
    __syncthreads();

    int warp = tid >> 5, lane = tid & 31;
    int r0 = blockIdx.x * 32 + warp * 4;
    const float* A0 = A + (size_t)(b * Nn + r0) * Nn;

    float acc[4][Ee];
#pragma unroll
    for (int r = 0; r < 4; r++)
#pragma unroll
        for (int e = 0; e < Ee; e++) acc[r][e] = 0.f;

#pragma unroll 4
    for (int js = 0; js < 32; js++) {
        int jj = js * 32 + lane;
        float a0 = A0[jj];
        float a1 = A0[Nn + jj];
        float a2 = A0[2 * Nn + jj];
        float a3 = A0[3 * Nn + jj];
#pragma unroll
        for (int e = 0; e < Ee; e++) {
            float hv = sh[e * Nn + jj];
            acc[0][e] += a0 * hv;
            acc[1][e] += a1 * hv;
            acc[2][e] += a2 * hv;
            acc[3][e] += a3 * hv;
        }
    }

#pragma unroll
    for (int r = 0; r < 4; r++)
#pragma unroll
        for (int e = 0; e < Ee; e++) {
            float v = acc[r][e];
            v += __shfl_xor_sync(0xffffffffu, v, 16);
            v += __shfl_xor_sync(0xffffffffu, v, 8);
            v += __shfl_xor_sync(0xffffffffu, v, 4);
            v += __shfl_xor_sync(0xffffffffu, v, 2);
            v += __shfl_xor_sync(0xffffffffu, v, 1);
            acc[r][e] = v;
        }

    if (lane < Ee) {
        int e = lane;
        float ssum = 0.f;
#pragma unroll
        for (int r = 0; r < 4; r++) {
            int i = r0 + r;
            float embf[Ee];
#pragma unroll
            for (int f = 0; f < Ee; f++)
                embf[f] = fmaxf(g_base[(b * Nn + i) * Ee + f] + acc[r][f], 0.f);
            if (last) {
                emb_out[(b * Nn + i) * Ee + e] = embf[e];
                ssum += embf[e];
            }
            float hv = 0.f;
#pragma unroll
            for (int f = 0; f < Ee; f++) hv += wps[e * Ee + f] * embf[f];
            hout[(b * Ee + e) * Nn + i] = hv;
        }
        if (last) atomicAdd(&g_S[b * Ee + e], ssum);
    }
}

__global__ void __launch_bounds__(256) final_kernel(
    const float* __restrict__ emb,
    float* __restrict__ q,
    const float* __restrict__ wqr,
    const float* __restrict__ wall,
    const float* __restrict__ wact)
{
    int idx = blockIdx.x * 256 + threadIdx.x;
    int b = idx >> 10;
    float cb = 0.f;
#pragma unroll
    for (int f = 0; f < Ee; f++) {
        float t = 0.f;
#pragma unroll
        for (int e = 0; e < Ee; e++) t += wall[f * Ee + e] * g_S[b * Ee + e];
        cb += wqr[f] * t;
    }
    float qv = cb;
#pragma unroll
    for (int e = 0; e < Ee; e++) {
        float t = 0.f;
#pragma unroll
        for (int f = 0; f < Ee; f++) t += wqr[Ee + f] * wact[f * Ee + e];
        qv += t * emb[idx * Ee + e];
    }
    q[idx] = qv;
}

extern "C" void kernel_launch(void* const* d_in, const int* in_sizes, int n_in,
                              void* d_out, int out_size) {
    const float* features       = (const float*)d_in[0];
    const float* weights        = (const float*)d_in[1];
    const float* adjacency      = (const float*)d_in[2];
    const float* w_selected     = (const float*)d_in[3];
    const float* w_nbpriors     = (const float*)d_in[4];
    const float* w_nbweights    = (const float*)d_in[5];
    const float* w_nbweights_ew = (const float*)d_in[6];
    const float* w_q_reduc      = (const float*)d_in[7];
    const float* w_q_allembed   = (const float*)d_in[8];
    const float* w_q_action     = (const float*)d_in[9];

    float* out = (float*)d_out;
    float* q = out;                  // [B,N]
    float* emb_out = out + Bb * Nn;  // [B,N,E]

    stage_wp_kernel<<<1, 128>>>(w_nbpriors);
    colsum_kernel<<<dim3(4, 8, 8), 256>>>(weights);
    base_kernel<<<32, 256>>>(features, w_selected, w_nbweights,
                             w_nbweights_ew, w_nbpriors);

    dim3 ig(32, 8);
    iter_kernel<<<ig, 256>>>(adjacency, 0, emb_out, 0);  // iter 2
    iter_kernel<<<ig, 256>>>(adjacency, 1, emb_out, 0);  // iter 3
    iter_kernel<<<ig, 256>>>(adjacency, 0, emb_out, 0);  // iter 4
    iter_kernel<<<ig, 256>>>(adjacency, 1, emb_out, 1);  // iter 5 (last)

    final_kernel<<<32, 256>>>(emb_out, q, w_q_reduc, w_q_allembed, w_q_action);
}